// round 14
// baseline (speedup 1.0000x reference)
#include <cuda_runtime.h>
#include <cuda_fp16.h>
#include <math.h>
#include <stdint.h>

#define B_SZ   4096
#define H_SZ   256
#define K_SZ   16
#define D_SZ   512
#define IN_DIM 8
#define XP_DIM 64
#define LN_EPS 1e-5f

// GEMM tiling: CTA = 128 x 128 x 1 expert, 8 warps (2m x 4n), 64x32 each
#define BM 128
#define BN 128
#define BK 64
#define SA 72                     // A smem row stride (halves)
#define SB 136                    // B smem row stride (halves)
#define A_BYTES (BM * SA * 2)     // 18432
#define B_BYTES (BK * SB * 2)     // 17408
#define STAGE (A_BYTES + B_BYTES) // 35840
#define NSTAGE 3
#define GEMM_SMEM (NSTAGE * STAGE)  // 107520  (2 CTAs/SM)
#define NITER (D_SZ / BK)           // 8
#define SVC 136                     // epilogue C-tile row stride (halves)
#define NYB (D_SZ / BN)             // 4 n-blocks

// prep2 grid: w2cvt blocks then agen blocks
#define NB_W2   1024
#define NB_AGEN 1024

// ---------------- scratch -----------------------------------------------
__device__ __half g_raw[(size_t)B_SZ * K_SZ * D_SZ];   // POST-tanh h2 (64MB)
__device__ __half g_A[(size_t)K_SZ * B_SZ * D_SZ];     // tanh(x*w1+b1) fp16 (64MB)
__device__ float  g_gates[B_SZ * K_SZ];
__device__ __half g_Bhi[(size_t)K_SZ * D_SZ * D_SZ];   // w2 fp16, [k][d][e]
__device__ float  g_psum[NYB][B_SZ * K_SZ];            // per-n-block LN partials
__device__ float  g_psq[NYB][B_SZ * K_SZ];

// ---------------- helpers ------------------------------------------------
__device__ __forceinline__ float fast_tanh(float x) {     // ~1e-6 err, 2 MUFU
    float e = __expf(2.0f * x);
    return 1.0f - __fdividef(2.0f, e + 1.0f);
}

__device__ __forceinline__ float tanh_approx(float x) {   // 1 MUFU
    float y;
    asm("tanh.approx.f32 %0, %1;" : "=f"(y) : "f"(x));
    return y;
}

__device__ __forceinline__ uint32_t smem_u32(const void* p) {
    uint32_t a;
    asm("{ .reg .u64 t; cvta.to.shared.u64 t, %1; cvt.u32.u64 %0, t; }"
        : "=r"(a) : "l"(p));
    return a;
}

__device__ __forceinline__ void cp16(uint32_t dst, const void* src) {
    asm volatile("cp.async.cg.shared.global [%0], [%1], 16;" :: "r"(dst), "l"(src));
}

__device__ __forceinline__ void ldsm4(uint32_t* r, uint32_t a) {
    asm volatile("ldmatrix.sync.aligned.m8n8.x4.shared.b16 {%0,%1,%2,%3}, [%4];"
                 : "=r"(r[0]), "=r"(r[1]), "=r"(r[2]), "=r"(r[3]) : "r"(a));
}

__device__ __forceinline__ void ldsm4t(uint32_t* r, uint32_t a) {
    asm volatile("ldmatrix.sync.aligned.m8n8.x4.trans.shared.b16 {%0,%1,%2,%3}, [%4];"
                 : "=r"(r[0]), "=r"(r[1]), "=r"(r[2]), "=r"(r[3]) : "r"(a));
}

__device__ __forceinline__ void mma16816(float* c, const uint32_t* a,
                                         uint32_t b0, uint32_t b1) {
    asm volatile(
        "mma.sync.aligned.m16n8k16.row.col.f32.f16.f16.f32 "
        "{%0,%1,%2,%3}, {%4,%5,%6,%7}, {%8,%9}, {%0,%1,%2,%3};"
        : "+f"(c[0]), "+f"(c[1]), "+f"(c[2]), "+f"(c[3])
        : "r"(a[0]), "r"(a[1]), "r"(a[2]), "r"(a[3]), "r"(b0), "r"(b1));
}

// ---------------------------------------------------------------------------
// prep2: w2->fp16 (blocks 0..1023, coalesced) + agen (blocks 1024..2047).
// ---------------------------------------------------------------------------
__global__ void __launch_bounds__(256) prep2_kernel(
    const float* __restrict__ w2, const float* __restrict__ x_ext,
    const float* __restrict__ w1, const float* __restrict__ b1) {
    const int tid = threadIdx.x;
    const int bid = blockIdx.x;

    if (bid < NB_W2) {
        const float4* src = (const float4*)w2;
        uint2* dst = (uint2*)g_Bhi;
        int base = bid * 1024 + tid;
#pragma unroll
        for (int i = 0; i < 4; i++) {
            int idx = base + i * 256;
            float4 v = __ldcs(&src[idx]);
            __half2 h01 = __floats2half2_rn(v.x, v.y);
            __half2 h23 = __floats2half2_rn(v.z, v.w);
            uint2 u;
            u.x = *(uint32_t*)&h01;
            u.y = *(uint32_t*)&h23;
            dst[idx] = u;
        }
        return;
    }

    // ---- agen: g_A[k][b][d] = fp16(tanh(x*w1+b1)) ----
    __shared__ float sx[64];
    const int aid = bid - NB_W2;
    const int k = aid >> 6;
    const int b0 = (aid & 63) * 64;
    const int g = tid & 63, q = tid >> 6;

    if (tid < 64) sx[tid] = x_ext[(b0 + tid) * K_SZ + k];
    const float4 wa = *(const float4*)&w1[k * D_SZ + g * 8];
    const float4 wb = *(const float4*)&w1[k * D_SZ + g * 8 + 4];
    const float4 ba = *(const float4*)&b1[k * D_SZ + g * 8];
    const float4 bb = *(const float4*)&b1[k * D_SZ + g * 8 + 4];
    __syncthreads();

#pragma unroll 4
    for (int it = 0; it < 16; it++) {
        int m = q * 16 + it;
        float xv = sx[m];
        union { __half h[8]; uint4 u; } H;
        H.h[0] = __float2half_rn(tanh_approx(fmaf(xv, wa.x, ba.x)));
        H.h[1] = __float2half_rn(tanh_approx(fmaf(xv, wa.y, ba.y)));
        H.h[2] = __float2half_rn(tanh_approx(fmaf(xv, wa.z, ba.z)));
        H.h[3] = __float2half_rn(tanh_approx(fmaf(xv, wa.w, ba.w)));
        H.h[4] = __float2half_rn(tanh_approx(fmaf(xv, wb.x, bb.x)));
        H.h[5] = __float2half_rn(tanh_approx(fmaf(xv, wb.y, bb.y)));
        H.h[6] = __float2half_rn(tanh_approx(fmaf(xv, wb.z, bb.z)));
        H.h[7] = __float2half_rn(tanh_approx(fmaf(xv, wb.w, bb.w)));
        *(uint4*)(g_A + ((size_t)k * B_SZ + b0 + m) * D_SZ + g * 8) = H.u;
    }
}

// ---------------------------------------------------------------------------
// Gating branch (called from GEMM launch; uses dynamic smem). 16 rows/block.
// ---------------------------------------------------------------------------
__device__ void gating_branch(char* sm, int gid,
                              const float* __restrict__ h_prev,
                              const float* __restrict__ gw1,
                              const float* __restrict__ gb1,
                              const float* __restrict__ gw2,
                              const float* __restrict__ gb2) {
    // carve dynamic smem: hsT [256][20]f (20480B) | ts [16][256]f (16384B)
    // | gw2s [4096]f (16384B)  => 53248B <= GEMM_SMEM
    float (*hsT)[20] = (float(*)[20])sm;
    float (*ts)[H_SZ] = (float(*)[H_SZ])(sm + 20480);
    float* gw2s = (float*)(sm + 20480 + 16384);
    const int tid = threadIdx.x;
    const int b0 = gid * 16;

    for (int idx = tid; idx < 16 * H_SZ; idx += 256) {
        int r = idx >> 8, i = idx & 255;
        hsT[i][r] = h_prev[(b0 + r) * H_SZ + i];
    }
    for (int idx = tid; idx < H_SZ * K_SZ / 4; idx += 256)
        ((float4*)gw2s)[idx] = ((const float4*)gw2)[idx];
    __syncthreads();

    {
        const int j = tid;
        float acc[16];
        float bb = gb1[j];
#pragma unroll
        for (int r = 0; r < 16; r++) acc[r] = bb;
#pragma unroll 4
        for (int i = 0; i < H_SZ; i++) {
            float w = gw1[i * H_SZ + j];
            const float4* hp = (const float4*)&hsT[i][0];
            float4 a0 = hp[0], a1 = hp[1], a2 = hp[2], a3 = hp[3];
            acc[0]  = fmaf(a0.x, w, acc[0]);
            acc[1]  = fmaf(a0.y, w, acc[1]);
            acc[2]  = fmaf(a0.z, w, acc[2]);
            acc[3]  = fmaf(a0.w, w, acc[3]);
            acc[4]  = fmaf(a1.x, w, acc[4]);
            acc[5]  = fmaf(a1.y, w, acc[5]);
            acc[6]  = fmaf(a1.z, w, acc[6]);
            acc[7]  = fmaf(a1.w, w, acc[7]);
            acc[8]  = fmaf(a2.x, w, acc[8]);
            acc[9]  = fmaf(a2.y, w, acc[9]);
            acc[10] = fmaf(a2.z, w, acc[10]);
            acc[11] = fmaf(a2.w, w, acc[11]);
            acc[12] = fmaf(a3.x, w, acc[12]);
            acc[13] = fmaf(a3.y, w, acc[13]);
            acc[14] = fmaf(a3.z, w, acc[14]);
            acc[15] = fmaf(a3.w, w, acc[15]);
        }
#pragma unroll
        for (int r = 0; r < 16; r++) ts[r][j] = fast_tanh(acc[r]);
    }
    __syncthreads();

    {
        const int r = tid >> 4, kk = tid & 15;
        float l = gb2[kk];
#pragma unroll 8
        for (int i = 0; i < H_SZ; i += 4) {
            float4 t4 = *(const float4*)&ts[r][i];
            l = fmaf(t4.x, gw2s[(i + 0) * K_SZ + kk], l);
            l = fmaf(t4.y, gw2s[(i + 1) * K_SZ + kk], l);
            l = fmaf(t4.z, gw2s[(i + 2) * K_SZ + kk], l);
            l = fmaf(t4.w, gw2s[(i + 3) * K_SZ + kk], l);
        }
        float m = l;
#pragma unroll
        for (int o = 8; o > 0; o >>= 1)
            m = fmaxf(m, __shfl_xor_sync(0xffffffffu, m, o));
        float e = __expf(l - m);
        float s = e;
#pragma unroll
        for (int o = 8; o > 0; o >>= 1)
            s += __shfl_xor_sync(0xffffffffu, s, o);
        g_gates[(b0 + r) * K_SZ + kk] = e / s;
    }
}

// ---------------------------------------------------------------------------
// Expert GEMM (+ gating slices z=16,17): mainloop unchanged from R13.
// ---------------------------------------------------------------------------
__device__ __forceinline__ void cp_B(int c, int k, int n0, uint32_t stage) {
    const int tid = threadIdx.x;
    const __half* src = g_Bhi + ((size_t)(k * D_SZ + c * BK)) * D_SZ + n0;
    uint32_t bs = stage + A_BYTES;
#pragma unroll
    for (int i = 0; i < 4; i++) {
        int idx = tid + i * 256;
        int row = idx >> 4, ch = idx & 15;
        cp16(bs + row * (SB * 2) + ch * 16, src + (size_t)row * D_SZ + ch * 8);
    }
}

__device__ __forceinline__ void cp_A(int c, int k, int b0, uint32_t stage) {
    const int tid = threadIdx.x;
    const __half* src = g_A + ((size_t)k * B_SZ + b0) * D_SZ + c * BK;
#pragma unroll
    for (int i = 0; i < 4; i++) {
        int idx = tid + i * 256;
        int m = idx >> 3, ch = idx & 7;
        cp16(stage + m * (SA * 2) + ch * 16, src + (size_t)m * D_SZ + ch * 8);
    }
}

__global__ void __launch_bounds__(256, 2)
expert_gemm_kernel(const float* __restrict__ b2,
                   const float* __restrict__ h_prev,
                   const float* __restrict__ gw1, const float* __restrict__ gb1,
                   const float* __restrict__ gw2, const float* __restrict__ gb2) {
    extern __shared__ __align__(128) char sm[];
    __shared__ float s_b2[BN];

    if (blockIdx.z >= K_SZ) {
        int gid = (int)((blockIdx.z - K_SZ) * gridDim.x * gridDim.y +
                        blockIdx.y * gridDim.x + blockIdx.x);
        gating_branch(sm, gid, h_prev, gw1, gb1, gw2, gb2);
        return;
    }

    const int tid = threadIdx.x, wid = tid >> 5, lane = tid & 31;
    const int b0 = blockIdx.x * BM, ny = blockIdx.y, k = blockIdx.z;
    const int n0 = ny * BN;
    const int wm = (wid >> 2) * 64, wn = (wid & 3) * 32;
    const uint32_t smb = smem_u32(sm);

    if (tid < BN) s_b2[tid] = b2[k * D_SZ + n0 + tid];

    const int row16 = (lane & 7) + ((lane >> 3) & 1) * 8;
    const int seg8  = ((lane >> 4) & 1) * 8;

    float acc[4][4][4];
#pragma unroll
    for (int a = 0; a < 4; a++)
#pragma unroll
        for (int b = 0; b < 4; b++)
#pragma unroll
            for (int q = 0; q < 4; q++) acc[a][b][q] = 0.0f;

    // prologue: stages 0,1
#pragma unroll
    for (int s = 0; s < 2; s++) {
        uint32_t st = smb + (uint32_t)s * STAGE;
        cp_A(s, k, b0, st);
        cp_B(s, k, n0, st);
        asm volatile("cp.async.commit_group;");
    }

    for (int c = 0; c < NITER; c++) {
        const uint32_t st = smb + (uint32_t)(c % NSTAGE) * STAGE;
        if (c < NITER - 1)
            asm volatile("cp.async.wait_group 1;" ::: "memory");
        else
            asm volatile("cp.async.wait_group 0;" ::: "memory");
        __syncthreads();

        if (c + 2 < NITER) {
            const uint32_t nst = smb + (uint32_t)((c + 2) % NSTAGE) * STAGE;
            cp_A(c + 2, k, b0, nst);
            cp_B(c + 2, k, n0, nst);
            asm volatile("cp.async.commit_group;");
        }

        const uint32_t As = st, Bh = st + A_BYTES;
#pragma unroll
        for (int kk = 0; kk < 4; kk++) {
            uint32_t ah[4][4];
#pragma unroll
            for (int mb = 0; mb < 4; mb++)
                ldsm4(ah[mb], As + (uint32_t)((wm + mb * 16 + row16) * (SA * 2) +
                                              (kk * 16 + seg8) * 2));
#pragma unroll
            for (int p = 0; p < 2; p++) {
                uint32_t bh[4];
                ldsm4t(bh, Bh + (uint32_t)((kk * 16 + row16) * (SB * 2) +
                                           (wn + p * 16 + seg8) * 2));
#pragma unroll
                for (int mb = 0; mb < 4; mb++) {
                    mma16816(acc[mb][2 * p],     ah[mb], bh[0], bh[1]);
                    mma16816(acc[mb][2 * p + 1], ah[mb], bh[2], bh[3]);
                }
            }
        }
    }

    // Epilogue: tanh -> smem C tile + per-row partial stats.
    __syncthreads();
    {
        __half* cs = (__half*)sm;          // [BM][SVC] = 34816B
        float* s_ps = (float*)(sm + 35840);            // [128][4]
        float* s_pq = (float*)(sm + 35840 + 2048);     // [128][4]
        const int q = lane >> 2, c2 = (lane & 3) * 2;
        const int wj = wid & 3;
#pragma unroll
        for (int mb = 0; mb < 4; mb++) {
            const int r0 = wm + mb * 16 + q;
            float ps0 = 0.f, ps1 = 0.f, pq0 = 0.f, pq1 = 0.f;
#pragma unroll
            for (int nb = 0; nb < 4; nb++) {
                const int e = wn + nb * 8 + c2;
                float bb0 = s_b2[e], bb1 = s_b2[e + 1];
                float v0 = fast_tanh(acc[mb][nb][0] + bb0);
                float v1 = fast_tanh(acc[mb][nb][1] + bb1);
                float v2 = fast_tanh(acc[mb][nb][2] + bb0);
                float v3 = fast_tanh(acc[mb][nb][3] + bb1);
                *(__half2*)&cs[r0 * SVC + e]       = __floats2half2_rn(v0, v1);
                *(__half2*)&cs[(r0 + 8) * SVC + e] = __floats2half2_rn(v2, v3);
                ps0 += v0 + v1; ps1 += v2 + v3;
                pq0 += v0 * v0 + v1 * v1; pq1 += v2 * v2 + v3 * v3;
            }
            ps0 += __shfl_xor_sync(0xffffffffu, ps0, 1);
            ps0 += __shfl_xor_sync(0xffffffffu, ps0, 2);
            pq0 += __shfl_xor_sync(0xffffffffu, pq0, 1);
            pq0 += __shfl_xor_sync(0xffffffffu, pq0, 2);
            ps1 += __shfl_xor_sync(0xffffffffu, ps1, 1);
            ps1 += __shfl_xor_sync(0xffffffffu, ps1, 2);
            pq1 += __shfl_xor_sync(0xffffffffu, pq1, 1);
            pq1 += __shfl_xor_sync(0xffffffffu, pq1, 2);
            if ((lane & 3) == 0) {
                s_ps[r0 * 4 + wj] = ps0;
                s_pq[r0 * 4 + wj] = pq0;
                s_ps[(r0 + 8) * 4 + wj] = ps1;
                s_pq[(r0 + 8) * 4 + wj] = pq1;
            }
        }
        __syncthreads();
#pragma unroll
        for (int i = 0; i < 8; i++) {
            int idx = tid + i * 256;
            int row = idx >> 4, seg = idx & 15;
            uint4 v = *(uint4*)&cs[row * SVC + seg * 8];
            *(uint4*)&g_raw[((size_t)(b0 + row) * K_SZ + k) * D_SZ + n0 + seg * 8] = v;
        }
        if (tid < BM) {
            float su = s_ps[tid * 4] + s_ps[tid * 4 + 1] +
                       s_ps[tid * 4 + 2] + s_ps[tid * 4 + 3];
            float sq = s_pq[tid * 4] + s_pq[tid * 4 + 1] +
                       s_pq[tid * 4 + 2] + s_pq[tid * 4 + 3];
            g_psum[ny][(b0 + tid) * K_SZ + k] = su;
            g_psq[ny][(b0 + tid) * K_SZ + k] = sq;
        }
    }
}

// ---------------------------------------------------------------------------
// Combine: stats from GEMM partials; weighted sum straight from g_raw.
// ---------------------------------------------------------------------------
__global__ void __launch_bounds__(256) combine_kernel(
    const float* __restrict__ x_l, const float* __restrict__ ln_g,
    const float* __restrict__ ln_b, const float* __restrict__ theta0,
    float* __restrict__ out) {
    __shared__ float th[D_SZ];
    __shared__ float s_a[K_SZ], s_am[K_SZ];
    const int b = blockIdx.x;
    const int tid = threadIdx.x;

    if (tid < K_SZ) {
        int idx = b * K_SZ + tid;
        float su = g_psum[0][idx] + g_psum[1][idx] +
                   g_psum[2][idx] + g_psum[3][idx];
        float sq = g_psq[0][idx] + g_psq[1][idx] +
                   g_psq[2][idx] + g_psq[3][idx];
        float mu = su * (1.0f / (float)D_SZ);
        float var = sq * (1.0f / (float)D_SZ) - mu * mu;
        float rs = rsqrtf(var + LN_EPS);
        float a = g_gates[idx] * rs;
        s_a[tid] = a;
        s_am[tid] = a * mu;
    }
    __syncthreads();

    float cc = 0.0f;
#pragma unroll
    for (int kk = 0; kk < K_SZ; kk++) cc += s_am[kk];

    const __half2* rawb = (const __half2*)&g_raw[(size_t)b * K_SZ * D_SZ];
    {
        float ax = 0.0f, ay = 0.0f;
#pragma unroll
        for (int kk = 0; kk < K_SZ; kk++) {
            __half2 h = __ldcs(&rawb[kk * (D_SZ / 2) + tid]);
            float2 f = __half22float2(h);
            ax = fmaf(s_a[kk], f.x, ax);
            ay = fmaf(s_a[kk], f.y, ay);
        }
        float2 lg = *(const float2*)&ln_g[2 * tid];
        float2 lb = *(const float2*)&ln_b[2 * tid];
        float2 t0 = *(const float2*)&theta0[2 * tid];
        float tx = fmaf(lg.x, ax - cc, lb.x) + t0.x;
        float ty = fmaf(lg.y, ay - cc, lb.y) + t0.y;
        th[2 * tid] = tx;
        th[2 * tid + 1] = ty;
        *(float2*)&out[(size_t)B_SZ * XP_DIM + (size_t)b * D_SZ + 2 * tid] =
            make_float2(tx, ty);
    }
    __syncthreads();

    if (tid < XP_DIM) {
        float xp = 0.0f;
#pragma unroll
        for (int i = 0; i < IN_DIM; i++)
            xp = fmaf(x_l[b * IN_DIM + i], th[i * XP_DIM + tid], xp);
        out[b * XP_DIM + tid] = xp;
    }
}

// ---------------------------------------------------------------------------
extern "C" void kernel_launch(void* const* d_in, const int* in_sizes, int n_in,
                              void* d_out, int out_size) {
    const float* h_prev = (const float*)d_in[0];
    const float* x_l    = (const float*)d_in[1];
    const float* x_ext  = (const float*)d_in[2];
    const float* w1     = (const float*)d_in[3];
    const float* b1     = (const float*)d_in[4];
    const float* w2     = (const float*)d_in[5];
    const float* b2     = (const float*)d_in[6];
    const float* gw1    = (const float*)d_in[7];
    const float* gb1    = (const float*)d_in[8];
    const float* gw2    = (const float*)d_in[9];
    const float* gb2    = (const float*)d_in[10];
    const float* ln_g   = (const float*)d_in[11];
    const float* ln_b   = (const float*)d_in[12];
    const float* th0    = (const float*)d_in[13];
    float* out = (float*)d_out;

    cudaFuncSetAttribute(expert_gemm_kernel,
                         cudaFuncAttributeMaxDynamicSharedMemorySize, GEMM_SMEM);

    prep2_kernel<<<NB_W2 + NB_AGEN, 256>>>(w2, x_ext, w1, b1);
    // z slices 0..15 = experts; 16..17 = 256 gating blocks (32x4x2)
    expert_gemm_kernel<<<dim3(B_SZ / BM, NYB, K_SZ + 2), 256, GEMM_SMEM>>>(
        b2, h_prev, gw1, gb1, gw2, gb2);
    combine_kernel<<<B_SZ, 256>>>(x_l, ln_g, ln_b, th0, out);
}

// round 15
// speedup vs baseline: 1.4628x; 1.4628x over previous
#include <cuda_runtime.h>
#include <cuda_fp16.h>
#include <math.h>
#include <stdint.h>

#define B_SZ   4096
#define H_SZ   256
#define K_SZ   16
#define D_SZ   512
#define IN_DIM 8
#define XP_DIM 64
#define LN_EPS 1e-5f

// GEMM tiling: CTA = 128 x 128 x 1 expert, 8 warps (2m x 4n), 64x32 each
#define BM 128
#define BN 128
#define BK 64
#define SA 72                     // A smem row stride (halves)
#define SB 136                    // B smem row stride (halves)
#define A_BYTES (BM * SA * 2)     // 18432
#define B_BYTES (BK * SB * 2)     // 17408
#define STAGE (A_BYTES + B_BYTES) // 35840
#define NSTAGE 3
#define GEMM_SMEM (NSTAGE * STAGE)  // 107520  (2 CTAs/SM)
#define NITER (D_SZ / BK)           // 8
#define SVC 136                     // epilogue C-tile row stride (halves)
#define NYB (D_SZ / BN)             // 4 n-blocks

// fused prep grid: gating(256) + w2cvt(1024) + agen(1024)
#define NB_GATE 256
#define NB_W2   1024
#define NB_AGEN 1024
#define NB_PREP (NB_GATE + NB_W2 + NB_AGEN)

// ---------------- scratch -----------------------------------------------
__device__ __half g_raw[(size_t)B_SZ * K_SZ * D_SZ];   // POST-tanh h2 (64MB)
__device__ __half g_A[(size_t)K_SZ * B_SZ * D_SZ];     // tanh(x*w1+b1) fp16 (64MB)
__device__ float  g_gates[B_SZ * K_SZ];
__device__ __half g_Bhi[(size_t)K_SZ * D_SZ * D_SZ];   // w2 fp16, [k][d][e]
__device__ float  g_psum[NYB][B_SZ * K_SZ];            // per-n-block LN partials
__device__ float  g_psq[NYB][B_SZ * K_SZ];

// ---------------- helpers ------------------------------------------------
__device__ __forceinline__ float fast_tanh(float x) {     // ~1e-6 err, 2 MUFU
    float e = __expf(2.0f * x);
    return 1.0f - __fdividef(2.0f, e + 1.0f);
}

__device__ __forceinline__ float tanh_approx(float x) {   // 1 MUFU
    float y;
    asm("tanh.approx.f32 %0, %1;" : "=f"(y) : "f"(x));
    return y;
}

__device__ __forceinline__ uint32_t smem_u32(const void* p) {
    uint32_t a;
    asm("{ .reg .u64 t; cvta.to.shared.u64 t, %1; cvt.u32.u64 %0, t; }"
        : "=r"(a) : "l"(p));
    return a;
}

__device__ __forceinline__ void cp16(uint32_t dst, const void* src) {
    asm volatile("cp.async.cg.shared.global [%0], [%1], 16;" :: "r"(dst), "l"(src));
}

__device__ __forceinline__ void ldsm4(uint32_t* r, uint32_t a) {
    asm volatile("ldmatrix.sync.aligned.m8n8.x4.shared.b16 {%0,%1,%2,%3}, [%4];"
                 : "=r"(r[0]), "=r"(r[1]), "=r"(r[2]), "=r"(r[3]) : "r"(a));
}

__device__ __forceinline__ void ldsm4t(uint32_t* r, uint32_t a) {
    asm volatile("ldmatrix.sync.aligned.m8n8.x4.trans.shared.b16 {%0,%1,%2,%3}, [%4];"
                 : "=r"(r[0]), "=r"(r[1]), "=r"(r[2]), "=r"(r[3]) : "r"(a));
}

__device__ __forceinline__ void mma16816(float* c, const uint32_t* a,
                                         uint32_t b0, uint32_t b1) {
    asm volatile(
        "mma.sync.aligned.m16n8k16.row.col.f32.f16.f16.f32 "
        "{%0,%1,%2,%3}, {%4,%5,%6,%7}, {%8,%9}, {%0,%1,%2,%3};"
        : "+f"(c[0]), "+f"(c[1]), "+f"(c[2]), "+f"(c[3])
        : "r"(a[0]), "r"(a[1]), "r"(a[2]), "r"(a[3]), "r"(b0), "r"(b1));
}

// ---------------------------------------------------------------------------
// Fused prep: gating (0..255) + w2cvt coalesced (256..1279) + agen (1280..2303)
// ---------------------------------------------------------------------------
__global__ void __launch_bounds__(256) prep_kernel(
    const float* __restrict__ w2, const float* __restrict__ x_ext,
    const float* __restrict__ w1, const float* __restrict__ b1,
    const float* __restrict__ h_prev, const float* __restrict__ gw1,
    const float* __restrict__ gb1, const float* __restrict__ gw2,
    const float* __restrict__ gb2) {
    __shared__ float hsT[H_SZ][20];
    __shared__ float ts[16][H_SZ];
    __shared__ float gw2s[H_SZ * K_SZ];
    const int tid = threadIdx.x;
    const int bid = blockIdx.x;

    if (bid >= NB_GATE + NB_W2) {
        // ---- agen: g_A[k][b][d] = fp16(tanh(x*w1+b1)) ----
        float* sx = (float*)ts;            // reuse static smem (64 floats)
        const int aid = bid - (NB_GATE + NB_W2);
        const int k = aid >> 6;
        const int b0 = (aid & 63) * 64;
        const int g = tid & 63, q = tid >> 6;

        if (tid < 64) sx[tid] = x_ext[(b0 + tid) * K_SZ + k];
        const float4 wa = *(const float4*)&w1[k * D_SZ + g * 8];
        const float4 wb = *(const float4*)&w1[k * D_SZ + g * 8 + 4];
        const float4 ba = *(const float4*)&b1[k * D_SZ + g * 8];
        const float4 bb = *(const float4*)&b1[k * D_SZ + g * 8 + 4];
        __syncthreads();

#pragma unroll 4
        for (int it = 0; it < 16; it++) {
            int m = q * 16 + it;
            float xv = sx[m];
            union { __half h[8]; uint4 u; } H;
            H.h[0] = __float2half_rn(tanh_approx(fmaf(xv, wa.x, ba.x)));
            H.h[1] = __float2half_rn(tanh_approx(fmaf(xv, wa.y, ba.y)));
            H.h[2] = __float2half_rn(tanh_approx(fmaf(xv, wa.z, ba.z)));
            H.h[3] = __float2half_rn(tanh_approx(fmaf(xv, wa.w, ba.w)));
            H.h[4] = __float2half_rn(tanh_approx(fmaf(xv, wb.x, bb.x)));
            H.h[5] = __float2half_rn(tanh_approx(fmaf(xv, wb.y, bb.y)));
            H.h[6] = __float2half_rn(tanh_approx(fmaf(xv, wb.z, bb.z)));
            H.h[7] = __float2half_rn(tanh_approx(fmaf(xv, wb.w, bb.w)));
            *(uint4*)(g_A + ((size_t)k * B_SZ + b0 + m) * D_SZ + g * 8) = H.u;
        }
        return;
    }

    if (bid >= NB_GATE) {
        // ---- w2 fp32 -> fp16, thread-consecutive float4 (coalesced) ----
        const float4* src = (const float4*)w2;
        uint2* dst = (uint2*)g_Bhi;
        int base = (bid - NB_GATE) * 1024 + tid;
#pragma unroll
        for (int i = 0; i < 4; i++) {
            int idx = base + i * 256;
            float4 v = __ldcs(&src[idx]);
            __half2 h01 = __floats2half2_rn(v.x, v.y);
            __half2 h23 = __floats2half2_rn(v.z, v.w);
            uint2 u;
            u.x = *(uint32_t*)&h01;
            u.y = *(uint32_t*)&h23;
            dst[idx] = u;
        }
        return;
    }

    // ---- gating: 16 rows per block ----
    const int b0 = bid * 16;

    for (int idx = tid; idx < 16 * H_SZ; idx += 256) {
        int r = idx >> 8, i = idx & 255;
        hsT[i][r] = h_prev[(b0 + r) * H_SZ + i];
    }
    for (int idx = tid; idx < H_SZ * K_SZ / 4; idx += 256)
        ((float4*)gw2s)[idx] = ((const float4*)gw2)[idx];
    __syncthreads();

    {
        const int j = tid;
        float acc[16];
        float bb = gb1[j];
#pragma unroll
        for (int r = 0; r < 16; r++) acc[r] = bb;
#pragma unroll 4
        for (int i = 0; i < H_SZ; i++) {
            float w = gw1[i * H_SZ + j];
            const float4* hp = (const float4*)&hsT[i][0];
            float4 a0 = hp[0], a1 = hp[1], a2 = hp[2], a3 = hp[3];
            acc[0]  = fmaf(a0.x, w, acc[0]);
            acc[1]  = fmaf(a0.y, w, acc[1]);
            acc[2]  = fmaf(a0.z, w, acc[2]);
            acc[3]  = fmaf(a0.w, w, acc[3]);
            acc[4]  = fmaf(a1.x, w, acc[4]);
            acc[5]  = fmaf(a1.y, w, acc[5]);
            acc[6]  = fmaf(a1.z, w, acc[6]);
            acc[7]  = fmaf(a1.w, w, acc[7]);
            acc[8]  = fmaf(a2.x, w, acc[8]);
            acc[9]  = fmaf(a2.y, w, acc[9]);
            acc[10] = fmaf(a2.z, w, acc[10]);
            acc[11] = fmaf(a2.w, w, acc[11]);
            acc[12] = fmaf(a3.x, w, acc[12]);
            acc[13] = fmaf(a3.y, w, acc[13]);
            acc[14] = fmaf(a3.z, w, acc[14]);
            acc[15] = fmaf(a3.w, w, acc[15]);
        }
#pragma unroll
        for (int r = 0; r < 16; r++) ts[r][j] = fast_tanh(acc[r]);
    }
    __syncthreads();

    {
        const int r = tid >> 4, kk = tid & 15;
        float l = gb2[kk];
#pragma unroll 8
        for (int i = 0; i < H_SZ; i += 4) {
            float4 t4 = *(const float4*)&ts[r][i];
            l = fmaf(t4.x, gw2s[(i + 0) * K_SZ + kk], l);
            l = fmaf(t4.y, gw2s[(i + 1) * K_SZ + kk], l);
            l = fmaf(t4.z, gw2s[(i + 2) * K_SZ + kk], l);
            l = fmaf(t4.w, gw2s[(i + 3) * K_SZ + kk], l);
        }
        float m = l;
#pragma unroll
        for (int o = 8; o > 0; o >>= 1)
            m = fmaxf(m, __shfl_xor_sync(0xffffffffu, m, o));
        float e = __expf(l - m);
        float s = e;
#pragma unroll
        for (int o = 8; o > 0; o >>= 1)
            s += __shfl_xor_sync(0xffffffffu, s, o);
        g_gates[(b0 + r) * K_SZ + kk] = e / s;
    }
}

// ---------------------------------------------------------------------------
// Expert GEMM (byte-identical mainloop to R13): pure cp/ldsm/mma; epilogue =
// tanh + smem C-tile (coalesced STG.128) + per-row LN partials.
// ---------------------------------------------------------------------------
__device__ __forceinline__ void cp_B(int c, int k, int n0, uint32_t stage) {
    const int tid = threadIdx.x;
    const __half* src = g_Bhi + ((size_t)(k * D_SZ + c * BK)) * D_SZ + n0;
    uint32_t bs = stage + A_BYTES;
#pragma unroll
    for (int i = 0; i < 4; i++) {
        int idx = tid + i * 256;
        int row = idx >> 4, ch = idx & 15;
        cp16(bs + row * (SB * 2) + ch * 16, src + (size_t)row * D_SZ + ch * 8);
    }
}

__device__ __forceinline__ void cp_A(int c, int k, int b0, uint32_t stage) {
    const int tid = threadIdx.x;
    const __half* src = g_A + ((size_t)k * B_SZ + b0) * D_SZ + c * BK;
#pragma unroll
    for (int i = 0; i < 4; i++) {
        int idx = tid + i * 256;
        int m = idx >> 3, ch = idx & 7;
        cp16(stage + m * (SA * 2) + ch * 16, src + (size_t)m * D_SZ + ch * 8);
    }
}

__global__ void __launch_bounds__(256, 2)
expert_gemm_kernel(const float* __restrict__ b2) {
    extern __shared__ __align__(128) char sm[];
    __shared__ float s_b2[BN];

    const int tid = threadIdx.x, wid = tid >> 5, lane = tid & 31;
    const int b0 = blockIdx.x * BM, ny = blockIdx.y, k = blockIdx.z;
    const int n0 = ny * BN;
    const int wm = (wid >> 2) * 64, wn = (wid & 3) * 32;
    const uint32_t smb = smem_u32(sm);

    if (tid < BN) s_b2[tid] = b2[k * D_SZ + n0 + tid];

    const int row16 = (lane & 7) + ((lane >> 3) & 1) * 8;
    const int seg8  = ((lane >> 4) & 1) * 8;

    float acc[4][4][4];
#pragma unroll
    for (int a = 0; a < 4; a++)
#pragma unroll
        for (int b = 0; b < 4; b++)
#pragma unroll
            for (int q = 0; q < 4; q++) acc[a][b][q] = 0.0f;

    // prologue: stages 0,1
#pragma unroll
    for (int s = 0; s < 2; s++) {
        uint32_t st = smb + (uint32_t)s * STAGE;
        cp_A(s, k, b0, st);
        cp_B(s, k, n0, st);
        asm volatile("cp.async.commit_group;");
    }

    for (int c = 0; c < NITER; c++) {
        const uint32_t st = smb + (uint32_t)(c % NSTAGE) * STAGE;
        if (c < NITER - 1)
            asm volatile("cp.async.wait_group 1;" ::: "memory");
        else
            asm volatile("cp.async.wait_group 0;" ::: "memory");
        __syncthreads();

        if (c + 2 < NITER) {
            const uint32_t nst = smb + (uint32_t)((c + 2) % NSTAGE) * STAGE;
            cp_A(c + 2, k, b0, nst);
            cp_B(c + 2, k, n0, nst);
            asm volatile("cp.async.commit_group;");
        }

        const uint32_t As = st, Bh = st + A_BYTES;
#pragma unroll
        for (int kk = 0; kk < 4; kk++) {
            uint32_t ah[4][4];
#pragma unroll
            for (int mb = 0; mb < 4; mb++)
                ldsm4(ah[mb], As + (uint32_t)((wm + mb * 16 + row16) * (SA * 2) +
                                              (kk * 16 + seg8) * 2));
#pragma unroll
            for (int p = 0; p < 2; p++) {
                uint32_t bh[4];
                ldsm4t(bh, Bh + (uint32_t)((kk * 16 + row16) * (SB * 2) +
                                           (wn + p * 16 + seg8) * 2));
#pragma unroll
                for (int mb = 0; mb < 4; mb++) {
                    mma16816(acc[mb][2 * p],     ah[mb], bh[0], bh[1]);
                    mma16816(acc[mb][2 * p + 1], ah[mb], bh[2], bh[3]);
                }
            }
        }
    }

    // Epilogue: tanh -> smem C tile + per-row partial stats.
    __syncthreads();
    {
        __half* cs = (__half*)sm;          // [BM][SVC] = 34816B
        float* s_ps = (float*)(sm + 35840);            // [128][4]
        float* s_pq = (float*)(sm + 35840 + 2048);     // [128][4]
        const int q = lane >> 2, c2 = (lane & 3) * 2;
        const int wj = wid & 3;
#pragma unroll
        for (int mb = 0; mb < 4; mb++) {
            const int r0 = wm + mb * 16 + q;
            float ps0 = 0.f, ps1 = 0.f, pq0 = 0.f, pq1 = 0.f;
#pragma unroll
            for (int nb = 0; nb < 4; nb++) {
                const int e = wn + nb * 8 + c2;
                float bb0 = s_b2[e], bb1 = s_b2[e + 1];
                float v0 = fast_tanh(acc[mb][nb][0] + bb0);
                float v1 = fast_tanh(acc[mb][nb][1] + bb1);
                float v2 = fast_tanh(acc[mb][nb][2] + bb0);
                float v3 = fast_tanh(acc[mb][nb][3] + bb1);
                *(__half2*)&cs[r0 * SVC + e]       = __floats2half2_rn(v0, v1);
                *(__half2*)&cs[(r0 + 8) * SVC + e] = __floats2half2_rn(v2, v3);
                ps0 += v0 + v1; ps1 += v2 + v3;
                pq0 += v0 * v0 + v1 * v1; pq1 += v2 * v2 + v3 * v3;
            }
            ps0 += __shfl_xor_sync(0xffffffffu, ps0, 1);
            ps0 += __shfl_xor_sync(0xffffffffu, ps0, 2);
            pq0 += __shfl_xor_sync(0xffffffffu, pq0, 1);
            pq0 += __shfl_xor_sync(0xffffffffu, pq0, 2);
            ps1 += __shfl_xor_sync(0xffffffffu, ps1, 1);
            ps1 += __shfl_xor_sync(0xffffffffu, ps1, 2);
            pq1 += __shfl_xor_sync(0xffffffffu, pq1, 1);
            pq1 += __shfl_xor_sync(0xffffffffu, pq1, 2);
            if ((lane & 3) == 0) {
                s_ps[r0 * 4 + wj] = ps0;
                s_pq[r0 * 4 + wj] = pq0;
                s_ps[(r0 + 8) * 4 + wj] = ps1;
                s_pq[(r0 + 8) * 4 + wj] = pq1;
            }
        }
        __syncthreads();
#pragma unroll
        for (int i = 0; i < 8; i++) {
            int idx = tid + i * 256;
            int row = idx >> 4, seg = idx & 15;
            uint4 v = *(uint4*)&cs[row * SVC + seg * 8];
            *(uint4*)&g_raw[((size_t)(b0 + row) * K_SZ + k) * D_SZ + n0 + seg * 8] = v;
        }
        if (tid < BM) {
            float su = s_ps[tid * 4] + s_ps[tid * 4 + 1] +
                       s_ps[tid * 4 + 2] + s_ps[tid * 4 + 3];
            float sq = s_pq[tid * 4] + s_pq[tid * 4 + 1] +
                       s_pq[tid * 4 + 2] + s_pq[tid * 4 + 3];
            g_psum[ny][(b0 + tid) * K_SZ + k] = su;
            g_psq[ny][(b0 + tid) * K_SZ + k] = sq;
        }
    }
}

// ---------------------------------------------------------------------------
// Combine: stats from GEMM partials; weighted sum straight from g_raw.
// ---------------------------------------------------------------------------
__global__ void __launch_bounds__(256) combine_kernel(
    const float* __restrict__ x_l, const float* __restrict__ ln_g,
    const float* __restrict__ ln_b, const float* __restrict__ theta0,
    float* __restrict__ out) {
    __shared__ float th[D_SZ];
    __shared__ float s_a[K_SZ], s_am[K_SZ];
    const int b = blockIdx.x;
    const int tid = threadIdx.x;

    if (tid < K_SZ) {
        int idx = b * K_SZ + tid;
        float su = g_psum[0][idx] + g_psum[1][idx] +
                   g_psum[2][idx] + g_psum[3][idx];
        float sq = g_psq[0][idx] + g_psq[1][idx] +
                   g_psq[2][idx] + g_psq[3][idx];
        float mu = su * (1.0f / (float)D_SZ);
        float var = sq * (1.0f / (float)D_SZ) - mu * mu;
        float rs = rsqrtf(var + LN_EPS);
        float a = g_gates[idx] * rs;
        s_a[tid] = a;
        s_am[tid] = a * mu;
    }
    __syncthreads();

    float cc = 0.0f;
#pragma unroll
    for (int kk = 0; kk < K_SZ; kk++) cc += s_am[kk];

    const __half2* rawb = (const __half2*)&g_raw[(size_t)b * K_SZ * D_SZ];
    {
        float ax = 0.0f, ay = 0.0f;
#pragma unroll
        for (int kk = 0; kk < K_SZ; kk++) {
            __half2 h = __ldcs(&rawb[kk * (D_SZ / 2) + tid]);
            float2 f = __half22float2(h);
            ax = fmaf(s_a[kk], f.x, ax);
            ay = fmaf(s_a[kk], f.y, ay);
        }
        float2 lg = *(const float2*)&ln_g[2 * tid];
        float2 lb = *(const float2*)&ln_b[2 * tid];
        float2 t0 = *(const float2*)&theta0[2 * tid];
        float tx = fmaf(lg.x, ax - cc, lb.x) + t0.x;
        float ty = fmaf(lg.y, ay - cc, lb.y) + t0.y;
        th[2 * tid] = tx;
        th[2 * tid + 1] = ty;
        *(float2*)&out[(size_t)B_SZ * XP_DIM + (size_t)b * D_SZ + 2 * tid] =
            make_float2(tx, ty);
    }
    __syncthreads();

    if (tid < XP_DIM) {
        float xp = 0.0f;
#pragma unroll
        for (int i = 0; i < IN_DIM; i++)
            xp = fmaf(x_l[b * IN_DIM + i], th[i * XP_DIM + tid], xp);
        out[b * XP_DIM + tid] = xp;
    }
}

// ---------------------------------------------------------------------------
extern "C" void kernel_launch(void* const* d_in, const int* in_sizes, int n_in,
                              void* d_out, int out_size) {
    const float* h_prev = (const float*)d_in[0];
    const float* x_l    = (const float*)d_in[1];
    const float* x_ext  = (const float*)d_in[2];
    const float* w1     = (const float*)d_in[3];
    const float* b1     = (const float*)d_in[4];
    const float* w2     = (const float*)d_in[5];
    const float* b2     = (const float*)d_in[6];
    const float* gw1    = (const float*)d_in[7];
    const float* gb1    = (const float*)d_in[8];
    const float* gw2    = (const float*)d_in[9];
    const float* gb2    = (const float*)d_in[10];
    const float* ln_g   = (const float*)d_in[11];
    const float* ln_b   = (const float*)d_in[12];
    const float* th0    = (const float*)d_in[13];
    float* out = (float*)d_out;

    cudaFuncSetAttribute(expert_gemm_kernel,
                         cudaFuncAttributeMaxDynamicSharedMemorySize, GEMM_SMEM);

    prep_kernel<<<NB_PREP, 256>>>(w2, x_ext, w1, b1, h_prev,
                                  gw1, gb1, gw2, gb2);
    expert_gemm_kernel<<<dim3(B_SZ / BM, NYB, K_SZ), 256, GEMM_SMEM>>>(b2);
    combine_kernel<<<B_SZ, 256>>>(x_l, ln_g, ln_b, th0, out);
}

// round 16
// speedup vs baseline: 1.4667x; 1.0027x over previous
#include <cuda_runtime.h>
#include <cuda_fp16.h>
#include <math.h>
#include <stdint.h>

#define B_SZ   4096
#define H_SZ   256
#define K_SZ   16
#define D_SZ   512
#define IN_DIM 8
#define XP_DIM 64
#define LN_EPS 1e-5f

// GEMM tiling: CTA = 128 x 128 x 1 expert, 8 warps (2m x 4n), 64x32 each
#define BM 128
#define BN 128
#define BK 64
#define SA 72                     // A smem row stride (halves)
#define SB 136                    // B smem row stride (halves)
#define A_BYTES (BM * SA * 2)     // 18432
#define B_BYTES (BK * SB * 2)     // 17408
#define STAGE (A_BYTES + B_BYTES) // 35840
#define NSTAGE 3
#define GEMM_SMEM (NSTAGE * STAGE)  // 107520  (2 CTAs/SM)
#define NITER (D_SZ / BK)           // 8
#define SVC 136                     // epilogue C-tile row stride (halves)
#define NYB (D_SZ / BN)             // 4 n-blocks

// fused prep grid: gating(512, 8 rows each) + w2cvt(1024) + agen(1024)
#define NB_GATE 512
#define NB_W2   1024
#define NB_AGEN 1024
#define NB_PREP (NB_GATE + NB_W2 + NB_AGEN)

// ---------------- scratch -----------------------------------------------
__device__ __half g_raw[(size_t)B_SZ * K_SZ * D_SZ];   // POST-tanh h2 (64MB)
__device__ __half g_A[(size_t)K_SZ * B_SZ * D_SZ];     // tanh(x*w1+b1) fp16 (64MB)
__device__ float  g_gates[B_SZ * K_SZ];
__device__ __half g_Bhi[(size_t)K_SZ * D_SZ * D_SZ];   // w2 fp16, [k][d][e]
__device__ float  g_psum[NYB][B_SZ * K_SZ];            // per-n-block LN partials
__device__ float  g_psq[NYB][B_SZ * K_SZ];

// ---------------- helpers ------------------------------------------------
__device__ __forceinline__ float fast_tanh(float x) {     // ~1e-6 err, 2 MUFU
    float e = __expf(2.0f * x);
    return 1.0f - __fdividef(2.0f, e + 1.0f);
}

__device__ __forceinline__ float tanh_approx(float x) {   // 1 MUFU
    float y;
    asm("tanh.approx.f32 %0, %1;" : "=f"(y) : "f"(x));
    return y;
}

__device__ __forceinline__ uint32_t smem_u32(const void* p) {
    uint32_t a;
    asm("{ .reg .u64 t; cvta.to.shared.u64 t, %1; cvt.u32.u64 %0, t; }"
        : "=r"(a) : "l"(p));
    return a;
}

__device__ __forceinline__ void cp16(uint32_t dst, const void* src) {
    asm volatile("cp.async.cg.shared.global [%0], [%1], 16;" :: "r"(dst), "l"(src));
}

__device__ __forceinline__ void ldsm4(uint32_t* r, uint32_t a) {
    asm volatile("ldmatrix.sync.aligned.m8n8.x4.shared.b16 {%0,%1,%2,%3}, [%4];"
                 : "=r"(r[0]), "=r"(r[1]), "=r"(r[2]), "=r"(r[3]) : "r"(a));
}

__device__ __forceinline__ void ldsm4t(uint32_t* r, uint32_t a) {
    asm volatile("ldmatrix.sync.aligned.m8n8.x4.trans.shared.b16 {%0,%1,%2,%3}, [%4];"
                 : "=r"(r[0]), "=r"(r[1]), "=r"(r[2]), "=r"(r[3]) : "r"(a));
}

__device__ __forceinline__ void mma16816(float* c, const uint32_t* a,
                                         uint32_t b0, uint32_t b1) {
    asm volatile(
        "mma.sync.aligned.m16n8k16.row.col.f32.f16.f16.f32 "
        "{%0,%1,%2,%3}, {%4,%5,%6,%7}, {%8,%9}, {%0,%1,%2,%3};"
        : "+f"(c[0]), "+f"(c[1]), "+f"(c[2]), "+f"(c[3])
        : "r"(a[0]), "r"(a[1]), "r"(a[2]), "r"(a[3]), "r"(b0), "r"(b1));
}

// ---------------------------------------------------------------------------
// Fused prep, LOW-SMEM (16KB): gating 8-rows/block (0..511) +
// w2cvt coalesced (512..1535) + agen (1536..2559)
// ---------------------------------------------------------------------------
__global__ void __launch_bounds__(256) prep_kernel(
    const float* __restrict__ w2, const float* __restrict__ x_ext,
    const float* __restrict__ w1, const float* __restrict__ b1,
    const float* __restrict__ h_prev, const float* __restrict__ gw1,
    const float* __restrict__ gb1, const float* __restrict__ gw2,
    const float* __restrict__ gb2) {
    __shared__ float hsT[H_SZ][8];       // 8KB  (broadcast reads, no pad)
    __shared__ float ts[8][H_SZ];        // 8KB
    const int tid = threadIdx.x;
    const int bid = blockIdx.x;

    if (bid >= NB_GATE + NB_W2) {
        // ---- agen: g_A[k][b][d] = fp16(tanh(x*w1+b1)) ----
        float* sx = (float*)ts;          // reuse (64 floats)
        const int aid = bid - (NB_GATE + NB_W2);
        const int k = aid >> 6;
        const int b0 = (aid & 63) * 64;
        const int g = tid & 63, q = tid >> 6;

        if (tid < 64) sx[tid] = x_ext[(b0 + tid) * K_SZ + k];
        const float4 wa = *(const float4*)&w1[k * D_SZ + g * 8];
        const float4 wb = *(const float4*)&w1[k * D_SZ + g * 8 + 4];
        const float4 ba = *(const float4*)&b1[k * D_SZ + g * 8];
        const float4 bb = *(const float4*)&b1[k * D_SZ + g * 8 + 4];
        __syncthreads();

#pragma unroll 4
        for (int it = 0; it < 16; it++) {
            int m = q * 16 + it;
            float xv = sx[m];
            union { __half h[8]; uint4 u; } H;
            H.h[0] = __float2half_rn(tanh_approx(fmaf(xv, wa.x, ba.x)));
            H.h[1] = __float2half_rn(tanh_approx(fmaf(xv, wa.y, ba.y)));
            H.h[2] = __float2half_rn(tanh_approx(fmaf(xv, wa.z, ba.z)));
            H.h[3] = __float2half_rn(tanh_approx(fmaf(xv, wa.w, ba.w)));
            H.h[4] = __float2half_rn(tanh_approx(fmaf(xv, wb.x, bb.x)));
            H.h[5] = __float2half_rn(tanh_approx(fmaf(xv, wb.y, bb.y)));
            H.h[6] = __float2half_rn(tanh_approx(fmaf(xv, wb.z, bb.z)));
            H.h[7] = __float2half_rn(tanh_approx(fmaf(xv, wb.w, bb.w)));
            *(uint4*)(g_A + ((size_t)k * B_SZ + b0 + m) * D_SZ + g * 8) = H.u;
        }
        return;
    }

    if (bid >= NB_GATE) {
        // ---- w2 fp32 -> fp16, thread-consecutive float4 (coalesced) ----
        const float4* src = (const float4*)w2;
        uint2* dst = (uint2*)g_Bhi;
        int base = (bid - NB_GATE) * 1024 + tid;
#pragma unroll
        for (int i = 0; i < 4; i++) {
            int idx = base + i * 256;
            float4 v = __ldcs(&src[idx]);
            __half2 h01 = __floats2half2_rn(v.x, v.y);
            __half2 h23 = __floats2half2_rn(v.z, v.w);
            uint2 u;
            u.x = *(uint32_t*)&h01;
            u.y = *(uint32_t*)&h23;
            dst[idx] = u;
        }
        return;
    }

    // ---- gating: 8 rows per block ----
    const int b0 = bid * 8;

    for (int idx = tid; idx < 8 * H_SZ; idx += 256) {
        int r = idx >> 8, i = idx & 255;
        hsT[i][r] = h_prev[(b0 + r) * H_SZ + i];
    }
    __syncthreads();

    {
        const int j = tid;
        float acc[8];
        float bb = gb1[j];
#pragma unroll
        for (int r = 0; r < 8; r++) acc[r] = bb;
#pragma unroll 4
        for (int i = 0; i < H_SZ; i++) {
            float w = gw1[i * H_SZ + j];
            const float4* hp = (const float4*)&hsT[i][0];
            float4 a0 = hp[0], a1 = hp[1];
            acc[0] = fmaf(a0.x, w, acc[0]);
            acc[1] = fmaf(a0.y, w, acc[1]);
            acc[2] = fmaf(a0.z, w, acc[2]);
            acc[3] = fmaf(a0.w, w, acc[3]);
            acc[4] = fmaf(a1.x, w, acc[4]);
            acc[5] = fmaf(a1.y, w, acc[5]);
            acc[6] = fmaf(a1.z, w, acc[6]);
            acc[7] = fmaf(a1.w, w, acc[7]);
        }
#pragma unroll
        for (int r = 0; r < 8; r++) ts[r][j] = fast_tanh(acc[r]);
    }
    __syncthreads();

    if (tid < 128) {
        const int r = tid >> 4, kk = tid & 15;
        float l = gb2[kk];
#pragma unroll 8
        for (int i = 0; i < H_SZ; i += 4) {
            float4 t4 = *(const float4*)&ts[r][i];
            l = fmaf(t4.x, gw2[(i + 0) * K_SZ + kk], l);
            l = fmaf(t4.y, gw2[(i + 1) * K_SZ + kk], l);
            l = fmaf(t4.z, gw2[(i + 2) * K_SZ + kk], l);
            l = fmaf(t4.w, gw2[(i + 3) * K_SZ + kk], l);
        }
        float m = l;
#pragma unroll
        for (int o = 8; o > 0; o >>= 1)
            m = fmaxf(m, __shfl_xor_sync(0xffffffffu, m, o));
        float e = __expf(l - m);
        float s = e;
#pragma unroll
        for (int o = 8; o > 0; o >>= 1)
            s += __shfl_xor_sync(0xffffffffu, s, o);
        g_gates[(b0 + r) * K_SZ + kk] = e / s;
    }
}

// ---------------------------------------------------------------------------
// Expert GEMM (byte-identical to R15): pure cp/ldsm/mma; epilogue = tanh +
// smem C-tile (coalesced STG.128) + per-row LN partials.
// ---------------------------------------------------------------------------
__device__ __forceinline__ void cp_B(int c, int k, int n0, uint32_t stage) {
    const int tid = threadIdx.x;
    const __half* src = g_Bhi + ((size_t)(k * D_SZ + c * BK)) * D_SZ + n0;
    uint32_t bs = stage + A_BYTES;
#pragma unroll
    for (int i = 0; i < 4; i++) {
        int idx = tid + i * 256;
        int row = idx >> 4, ch = idx & 15;
        cp16(bs + row * (SB * 2) + ch * 16, src + (size_t)row * D_SZ + ch * 8);
    }
}

__device__ __forceinline__ void cp_A(int c, int k, int b0, uint32_t stage) {
    const int tid = threadIdx.x;
    const __half* src = g_A + ((size_t)k * B_SZ + b0) * D_SZ + c * BK;
#pragma unroll
    for (int i = 0; i < 4; i++) {
        int idx = tid + i * 256;
        int m = idx >> 3, ch = idx & 7;
        cp16(stage + m * (SA * 2) + ch * 16, src + (size_t)m * D_SZ + ch * 8);
    }
}

__global__ void __launch_bounds__(256, 2)
expert_gemm_kernel(const float* __restrict__ b2) {
    extern __shared__ __align__(128) char sm[];
    __shared__ float s_b2[BN];

    const int tid = threadIdx.x, wid = tid >> 5, lane = tid & 31;
    const int b0 = blockIdx.x * BM, ny = blockIdx.y, k = blockIdx.z;
    const int n0 = ny * BN;
    const int wm = (wid >> 2) * 64, wn = (wid & 3) * 32;
    const uint32_t smb = smem_u32(sm);

    if (tid < BN) s_b2[tid] = b2[k * D_SZ + n0 + tid];

    const int row16 = (lane & 7) + ((lane >> 3) & 1) * 8;
    const int seg8  = ((lane >> 4) & 1) * 8;

    float acc[4][4][4];
#pragma unroll
    for (int a = 0; a < 4; a++)
#pragma unroll
        for (int b = 0; b < 4; b++)
#pragma unroll
            for (int q = 0; q < 4; q++) acc[a][b][q] = 0.0f;

    // prologue: stages 0,1
#pragma unroll
    for (int s = 0; s < 2; s++) {
        uint32_t st = smb + (uint32_t)s * STAGE;
        cp_A(s, k, b0, st);
        cp_B(s, k, n0, st);
        asm volatile("cp.async.commit_group;");
    }

    for (int c = 0; c < NITER; c++) {
        const uint32_t st = smb + (uint32_t)(c % NSTAGE) * STAGE;
        if (c < NITER - 1)
            asm volatile("cp.async.wait_group 1;" ::: "memory");
        else
            asm volatile("cp.async.wait_group 0;" ::: "memory");
        __syncthreads();

        if (c + 2 < NITER) {
            const uint32_t nst = smb + (uint32_t)((c + 2) % NSTAGE) * STAGE;
            cp_A(c + 2, k, b0, nst);
            cp_B(c + 2, k, n0, nst);
            asm volatile("cp.async.commit_group;");
        }

        const uint32_t As = st, Bh = st + A_BYTES;
#pragma unroll
        for (int kk = 0; kk < 4; kk++) {
            uint32_t ah[4][4];
#pragma unroll
            for (int mb = 0; mb < 4; mb++)
                ldsm4(ah[mb], As + (uint32_t)((wm + mb * 16 + row16) * (SA * 2) +
                                              (kk * 16 + seg8) * 2));
#pragma unroll
            for (int p = 0; p < 2; p++) {
                uint32_t bh[4];
                ldsm4t(bh, Bh + (uint32_t)((kk * 16 + row16) * (SB * 2) +
                                           (wn + p * 16 + seg8) * 2));
#pragma unroll
                for (int mb = 0; mb < 4; mb++) {
                    mma16816(acc[mb][2 * p],     ah[mb], bh[0], bh[1]);
                    mma16816(acc[mb][2 * p + 1], ah[mb], bh[2], bh[3]);
                }
            }
        }
    }

    // Epilogue: tanh -> smem C tile + per-row partial stats.
    __syncthreads();
    {
        __half* cs = (__half*)sm;          // [BM][SVC] = 34816B
        float* s_ps = (float*)(sm + 35840);            // [128][4]
        float* s_pq = (float*)(sm + 35840 + 2048);     // [128][4]
        const int q = lane >> 2, c2 = (lane & 3) * 2;
        const int wj = wid & 3;
#pragma unroll
        for (int mb = 0; mb < 4; mb++) {
            const int r0 = wm + mb * 16 + q;
            float ps0 = 0.f, ps1 = 0.f, pq0 = 0.f, pq1 = 0.f;
#pragma unroll
            for (int nb = 0; nb < 4; nb++) {
                const int e = wn + nb * 8 + c2;
                float bb0 = s_b2[e], bb1 = s_b2[e + 1];
                float v0 = fast_tanh(acc[mb][nb][0] + bb0);
                float v1 = fast_tanh(acc[mb][nb][1] + bb1);
                float v2 = fast_tanh(acc[mb][nb][2] + bb0);
                float v3 = fast_tanh(acc[mb][nb][3] + bb1);
                *(__half2*)&cs[r0 * SVC + e]       = __floats2half2_rn(v0, v1);
                *(__half2*)&cs[(r0 + 8) * SVC + e] = __floats2half2_rn(v2, v3);
                ps0 += v0 + v1; ps1 += v2 + v3;
                pq0 += v0 * v0 + v1 * v1; pq1 += v2 * v2 + v3 * v3;
            }
            ps0 += __shfl_xor_sync(0xffffffffu, ps0, 1);
            ps0 += __shfl_xor_sync(0xffffffffu, ps0, 2);
            pq0 += __shfl_xor_sync(0xffffffffu, pq0, 1);
            pq0 += __shfl_xor_sync(0xffffffffu, pq0, 2);
            ps1 += __shfl_xor_sync(0xffffffffu, ps1, 1);
            ps1 += __shfl_xor_sync(0xffffffffu, ps1, 2);
            pq1 += __shfl_xor_sync(0xffffffffu, pq1, 1);
            pq1 += __shfl_xor_sync(0xffffffffu, pq1, 2);
            if ((lane & 3) == 0) {
                s_ps[r0 * 4 + wj] = ps0;
                s_pq[r0 * 4 + wj] = pq0;
                s_ps[(r0 + 8) * 4 + wj] = ps1;
                s_pq[(r0 + 8) * 4 + wj] = pq1;
            }
        }
        __syncthreads();
#pragma unroll
        for (int i = 0; i < 8; i++) {
            int idx = tid + i * 256;
            int row = idx >> 4, seg = idx & 15;
            uint4 v = *(uint4*)&cs[row * SVC + seg * 8];
            *(uint4*)&g_raw[((size_t)(b0 + row) * K_SZ + k) * D_SZ + n0 + seg * 8] = v;
        }
        if (tid < BM) {
            float su = s_ps[tid * 4] + s_ps[tid * 4 + 1] +
                       s_ps[tid * 4 + 2] + s_ps[tid * 4 + 3];
            float sq = s_pq[tid * 4] + s_pq[tid * 4 + 1] +
                       s_pq[tid * 4 + 2] + s_pq[tid * 4 + 3];
            g_psum[ny][(b0 + tid) * K_SZ + k] = su;
            g_psq[ny][(b0 + tid) * K_SZ + k] = sq;
        }
    }
}

// ---------------------------------------------------------------------------
// Combine: stats from GEMM partials; weighted sum straight from g_raw.
// ---------------------------------------------------------------------------
__global__ void __launch_bounds__(256) combine_kernel(
    const float* __restrict__ x_l, const float* __restrict__ ln_g,
    const float* __restrict__ ln_b, const float* __restrict__ theta0,
    float* __restrict__ out) {
    __shared__ float th[D_SZ];
    __shared__ float s_a[K_SZ], s_am[K_SZ];
    const int b = blockIdx.x;
    const int tid = threadIdx.x;

    if (tid < K_SZ) {
        int idx = b * K_SZ + tid;
        float su = g_psum[0][idx] + g_psum[1][idx] +
                   g_psum[2][idx] + g_psum[3][idx];
        float sq = g_psq[0][idx] + g_psq[1][idx] +
                   g_psq[2][idx] + g_psq[3][idx];
        float mu = su * (1.0f / (float)D_SZ);
        float var = sq * (1.0f / (float)D_SZ) - mu * mu;
        float rs = rsqrtf(var + LN_EPS);
        float a = g_gates[idx] * rs;
        s_a[tid] = a;
        s_am[tid] = a * mu;
    }
    __syncthreads();

    float cc = 0.0f;
#pragma unroll
    for (int kk = 0; kk < K_SZ; kk++) cc += s_am[kk];

    const __half2* rawb = (const __half2*)&g_raw[(size_t)b * K_SZ * D_SZ];
    {
        float ax = 0.0f, ay = 0.0f;
#pragma unroll
        for (int kk = 0; kk < K_SZ; kk++) {
            __half2 h = __ldcs(&rawb[kk * (D_SZ / 2) + tid]);
            float2 f = __half22float2(h);
            ax = fmaf(s_a[kk], f.x, ax);
            ay = fmaf(s_a[kk], f.y, ay);
        }
        float2 lg = *(const float2*)&ln_g[2 * tid];
        float2 lb = *(const float2*)&ln_b[2 * tid];
        float2 t0 = *(const float2*)&theta0[2 * tid];
        float tx = fmaf(lg.x, ax - cc, lb.x) + t0.x;
        float ty = fmaf(lg.y, ay - cc, lb.y) + t0.y;
        th[2 * tid] = tx;
        th[2 * tid + 1] = ty;
        *(float2*)&out[(size_t)B_SZ * XP_DIM + (size_t)b * D_SZ + 2 * tid] =
            make_float2(tx, ty);
    }
    __syncthreads();

    if (tid < XP_DIM) {
        float xp = 0.0f;
#pragma unroll
        for (int i = 0; i < IN_DIM; i++)
            xp = fmaf(x_l[b * IN_DIM + i], th[i * XP_DIM + tid], xp);
        out[b * XP_DIM + tid] = xp;
    }
}

// ---------------------------------------------------------------------------
extern "C" void kernel_launch(void* const* d_in, const int* in_sizes, int n_in,
                              void* d_out, int out_size) {
    const float* h_prev = (const float*)d_in[0];
    const float* x_l    = (const float*)d_in[1];
    const float* x_ext  = (const float*)d_in[2];
    const float* w1     = (const float*)d_in[3];
    const float* b1     = (const float*)d_in[4];
    const float* w2     = (const float*)d_in[5];
    const float* b2     = (const float*)d_in[6];
    const float* gw1    = (const float*)d_in[7];
    const float* gb1    = (const float*)d_in[8];
    const float* gw2    = (const float*)d_in[9];
    const float* gb2    = (const float*)d_in[10];
    const float* ln_g   = (const float*)d_in[11];
    const float* ln_b   = (const float*)d_in[12];
    const float* th0    = (const float*)d_in[13];
    float* out = (float*)d_out;

    cudaFuncSetAttribute(expert_gemm_kernel,
                         cudaFuncAttributeMaxDynamicSharedMemorySize, GEMM_SMEM);

    prep_kernel<<<NB_PREP, 256>>>(w2, x_ext, w1, b1, h_prev,
                                  gw1, gb1, gw2, gb2);
    expert_gemm_kernel<<<dim3(B_SZ / BM, NYB, K_SZ), 256, GEMM_SMEM>>>(b2);
    combine_kernel<<<B_SZ, 256>>>(x_l, ln_g, ln_b, th0, out);
}

// round 17
// speedup vs baseline: 1.5505x; 1.0572x over previous
#include <cuda_runtime.h>
#include <cuda_fp16.h>
#include <math.h>
#include <stdint.h>

#define B_SZ   4096
#define H_SZ   256
#define K_SZ   16
#define D_SZ   512
#define IN_DIM 8
#define XP_DIM 64
#define LN_EPS 1e-5f

// GEMM tiling: CTA = 128 x 128 x 1 expert, 8 warps (2m x 4n), 64x32 each
#define BM 128
#define BN 128
#define BK 64
#define SA 72                     // A smem row stride (halves)
#define SB 136                    // B smem row stride (halves)
#define A_BYTES (BM * SA * 2)     // 18432
#define B_BYTES (BK * SB * 2)     // 17408
#define STAGE (A_BYTES + B_BYTES) // 35840
#define NSTAGE 3
#define GEMM_SMEM (NSTAGE * STAGE)  // 107520  (2 CTAs/SM)
#define NITER (D_SZ / BK)           // 8
#define SVC 136                     // epilogue C-tile row stride (halves)
#define NYB (D_SZ / BN)             // 4 n-blocks

// fused prep grid: gating(512, 8 rows) + w2cvt(2048) + agen(2048, 32 rows)
#define NB_GATE 512
#define NB_W2   2048
#define NB_AGEN 2048
#define NB_PREP (NB_GATE + NB_W2 + NB_AGEN)

// ---------------- scratch -----------------------------------------------
__device__ __half g_raw[(size_t)B_SZ * K_SZ * D_SZ];   // POST-tanh h2 (64MB)
__device__ __half g_A[(size_t)K_SZ * B_SZ * D_SZ];     // tanh(x*w1+b1) fp16 (64MB)
__device__ float  g_gates[B_SZ * K_SZ];
__device__ __half g_Bhi[(size_t)K_SZ * D_SZ * D_SZ];   // w2 fp16, [k][d][e]
__device__ float  g_psum[NYB][B_SZ * K_SZ];            // per-n-block LN partials
__device__ float  g_psq[NYB][B_SZ * K_SZ];

// ---------------- helpers ------------------------------------------------
__device__ __forceinline__ float fast_tanh(float x) {     // ~1e-6 err, 2 MUFU
    float e = __expf(2.0f * x);
    return 1.0f - __fdividef(2.0f, e + 1.0f);
}

__device__ __forceinline__ float tanh_approx(float x) {   // 1 MUFU
    float y;
    asm("tanh.approx.f32 %0, %1;" : "=f"(y) : "f"(x));
    return y;
}

__device__ __forceinline__ uint32_t smem_u32(const void* p) {
    uint32_t a;
    asm("{ .reg .u64 t; cvta.to.shared.u64 t, %1; cvt.u32.u64 %0, t; }"
        : "=r"(a) : "l"(p));
    return a;
}

__device__ __forceinline__ void cp16(uint32_t dst, const void* src) {
    asm volatile("cp.async.cg.shared.global [%0], [%1], 16;" :: "r"(dst), "l"(src));
}

__device__ __forceinline__ void ldsm4(uint32_t* r, uint32_t a) {
    asm volatile("ldmatrix.sync.aligned.m8n8.x4.shared.b16 {%0,%1,%2,%3}, [%4];"
                 : "=r"(r[0]), "=r"(r[1]), "=r"(r[2]), "=r"(r[3]) : "r"(a));
}

__device__ __forceinline__ void ldsm4t(uint32_t* r, uint32_t a) {
    asm volatile("ldmatrix.sync.aligned.m8n8.x4.trans.shared.b16 {%0,%1,%2,%3}, [%4];"
                 : "=r"(r[0]), "=r"(r[1]), "=r"(r[2]), "=r"(r[3]) : "r"(a));
}

__device__ __forceinline__ void mma16816(float* c, const uint32_t* a,
                                         uint32_t b0, uint32_t b1) {
    asm volatile(
        "mma.sync.aligned.m16n8k16.row.col.f32.f16.f16.f32 "
        "{%0,%1,%2,%3}, {%4,%5,%6,%7}, {%8,%9}, {%0,%1,%2,%3};"
        : "+f"(c[0]), "+f"(c[1]), "+f"(c[2]), "+f"(c[3])
        : "r"(a[0]), "r"(a[1]), "r"(a[2]), "r"(a[3]), "r"(b0), "r"(b1));
}

// ---------------------------------------------------------------------------
// Fused prep, LOW-SMEM (16KB), latency-balanced:
// gating 8-rows (0..511) + w2cvt 2 float4/thr (512..2559) + agen 32-rows
// (2560..4607).
// ---------------------------------------------------------------------------
__global__ void __launch_bounds__(256) prep_kernel(
    const float* __restrict__ w2, const float* __restrict__ x_ext,
    const float* __restrict__ w1, const float* __restrict__ b1,
    const float* __restrict__ h_prev, const float* __restrict__ gw1,
    const float* __restrict__ gb1, const float* __restrict__ gw2,
    const float* __restrict__ gb2) {
    __shared__ float hsT[H_SZ][8];       // 8KB  (broadcast reads)
    __shared__ float ts[8][H_SZ];        // 8KB
    const int tid = threadIdx.x;
    const int bid = blockIdx.x;

    if (bid >= NB_GATE + NB_W2) {
        // ---- agen: 32 rows/block, 8 iters/thread ----
        float* sx = (float*)ts;          // reuse (32 floats)
        const int aid = bid - (NB_GATE + NB_W2);
        const int k = aid >> 7;
        const int b0 = (aid & 127) * 32;
        const int g = tid & 63, q = tid >> 6;

        if (tid < 32) sx[tid] = x_ext[(b0 + tid) * K_SZ + k];
        const float4 wa = *(const float4*)&w1[k * D_SZ + g * 8];
        const float4 wb = *(const float4*)&w1[k * D_SZ + g * 8 + 4];
        const float4 ba = *(const float4*)&b1[k * D_SZ + g * 8];
        const float4 bb = *(const float4*)&b1[k * D_SZ + g * 8 + 4];
        __syncthreads();

#pragma unroll 8
        for (int it = 0; it < 8; it++) {
            int m = q * 8 + it;
            float xv = sx[m];
            union { __half h[8]; uint4 u; } H;
            H.h[0] = __float2half_rn(tanh_approx(fmaf(xv, wa.x, ba.x)));
            H.h[1] = __float2half_rn(tanh_approx(fmaf(xv, wa.y, ba.y)));
            H.h[2] = __float2half_rn(tanh_approx(fmaf(xv, wa.z, ba.z)));
            H.h[3] = __float2half_rn(tanh_approx(fmaf(xv, wa.w, ba.w)));
            H.h[4] = __float2half_rn(tanh_approx(fmaf(xv, wb.x, bb.x)));
            H.h[5] = __float2half_rn(tanh_approx(fmaf(xv, wb.y, bb.y)));
            H.h[6] = __float2half_rn(tanh_approx(fmaf(xv, wb.z, bb.z)));
            H.h[7] = __float2half_rn(tanh_approx(fmaf(xv, wb.w, bb.w)));
            *(uint4*)(g_A + ((size_t)k * B_SZ + b0 + m) * D_SZ + g * 8) = H.u;
        }
        return;
    }

    if (bid >= NB_GATE) {
        // ---- w2 fp32 -> fp16, thread-consecutive float4 (coalesced) ----
        const float4* src = (const float4*)w2;
        uint2* dst = (uint2*)g_Bhi;
        int base = (bid - NB_GATE) * 512 + tid;
#pragma unroll
        for (int i = 0; i < 2; i++) {
            int idx = base + i * 256;
            float4 v = __ldcs(&src[idx]);
            __half2 h01 = __floats2half2_rn(v.x, v.y);
            __half2 h23 = __floats2half2_rn(v.z, v.w);
            uint2 u;
            u.x = *(uint32_t*)&h01;
            u.y = *(uint32_t*)&h23;
            dst[idx] = u;
        }
        return;
    }

    // ---- gating: 8 rows per block, unroll 8 (deep LDG MLP) ----
    const int b0 = bid * 8;

    for (int idx = tid; idx < 8 * H_SZ; idx += 256) {
        int r = idx >> 8, i = idx & 255;
        hsT[i][r] = h_prev[(b0 + r) * H_SZ + i];
    }
    __syncthreads();

    {
        const int j = tid;
        float acc[8];
        float bb = gb1[j];
#pragma unroll
        for (int r = 0; r < 8; r++) acc[r] = bb;
#pragma unroll 8
        for (int i = 0; i < H_SZ; i++) {
            float w = gw1[i * H_SZ + j];
            const float4* hp = (const float4*)&hsT[i][0];
            float4 a0 = hp[0], a1 = hp[1];
            acc[0] = fmaf(a0.x, w, acc[0]);
            acc[1] = fmaf(a0.y, w, acc[1]);
            acc[2] = fmaf(a0.z, w, acc[2]);
            acc[3] = fmaf(a0.w, w, acc[3]);
            acc[4] = fmaf(a1.x, w, acc[4]);
            acc[5] = fmaf(a1.y, w, acc[5]);
            acc[6] = fmaf(a1.z, w, acc[6]);
            acc[7] = fmaf(a1.w, w, acc[7]);
        }
#pragma unroll
        for (int r = 0; r < 8; r++) ts[r][j] = fast_tanh(acc[r]);
    }
    __syncthreads();

    if (tid < 128) {
        const int r = tid >> 4, kk = tid & 15;
        float l = gb2[kk];
#pragma unroll 8
        for (int i = 0; i < H_SZ; i += 4) {
            float4 t4 = *(const float4*)&ts[r][i];
            l = fmaf(t4.x, gw2[(i + 0) * K_SZ + kk], l);
            l = fmaf(t4.y, gw2[(i + 1) * K_SZ + kk], l);
            l = fmaf(t4.z, gw2[(i + 2) * K_SZ + kk], l);
            l = fmaf(t4.w, gw2[(i + 3) * K_SZ + kk], l);
        }
        float m = l;
#pragma unroll
        for (int o = 8; o > 0; o >>= 1)
            m = fmaxf(m, __shfl_xor_sync(0xffffffffu, m, o));
        float e = __expf(l - m);
        float s = e;
#pragma unroll
        for (int o = 8; o > 0; o >>= 1)
            s += __shfl_xor_sync(0xffffffffu, s, o);
        g_gates[(b0 + r) * K_SZ + kk] = e / s;
    }
}

// ---------------------------------------------------------------------------
// Expert GEMM (byte-identical to R15/R16): pure cp/ldsm/mma; epilogue = tanh
// + smem C-tile (coalesced STG.128) + per-row LN partials.
// ---------------------------------------------------------------------------
__device__ __forceinline__ void cp_B(int c, int k, int n0, uint32_t stage) {
    const int tid = threadIdx.x;
    const __half* src = g_Bhi + ((size_t)(k * D_SZ + c * BK)) * D_SZ + n0;
    uint32_t bs = stage + A_BYTES;
#pragma unroll
    for (int i = 0; i < 4; i++) {
        int idx = tid + i * 256;
        int row = idx >> 4, ch = idx & 15;
        cp16(bs + row * (SB * 2) + ch * 16, src + (size_t)row * D_SZ + ch * 8);
    }
}

__device__ __forceinline__ void cp_A(int c, int k, int b0, uint32_t stage) {
    const int tid = threadIdx.x;
    const __half* src = g_A + ((size_t)k * B_SZ + b0) * D_SZ + c * BK;
#pragma unroll
    for (int i = 0; i < 4; i++) {
        int idx = tid + i * 256;
        int m = idx >> 3, ch = idx & 7;
        cp16(stage + m * (SA * 2) + ch * 16, src + (size_t)m * D_SZ + ch * 8);
    }
}

__global__ void __launch_bounds__(256, 2)
expert_gemm_kernel(const float* __restrict__ b2) {
    extern __shared__ __align__(128) char sm[];
    __shared__ float s_b2[BN];

    const int tid = threadIdx.x, wid = tid >> 5, lane = tid & 31;
    const int b0 = blockIdx.x * BM, ny = blockIdx.y, k = blockIdx.z;
    const int n0 = ny * BN;
    const int wm = (wid >> 2) * 64, wn = (wid & 3) * 32;
    const uint32_t smb = smem_u32(sm);

    if (tid < BN) s_b2[tid] = b2[k * D_SZ + n0 + tid];

    const int row16 = (lane & 7) + ((lane >> 3) & 1) * 8;
    const int seg8  = ((lane >> 4) & 1) * 8;

    float acc[4][4][4];
#pragma unroll
    for (int a = 0; a < 4; a++)
#pragma unroll
        for (int b = 0; b < 4; b++)
#pragma unroll
            for (int q = 0; q < 4; q++) acc[a][b][q] = 0.0f;

    // prologue: stages 0,1
#pragma unroll
    for (int s = 0; s < 2; s++) {
        uint32_t st = smb + (uint32_t)s * STAGE;
        cp_A(s, k, b0, st);
        cp_B(s, k, n0, st);
        asm volatile("cp.async.commit_group;");
    }

    for (int c = 0; c < NITER; c++) {
        const uint32_t st = smb + (uint32_t)(c % NSTAGE) * STAGE;
        if (c < NITER - 1)
            asm volatile("cp.async.wait_group 1;" ::: "memory");
        else
            asm volatile("cp.async.wait_group 0;" ::: "memory");
        __syncthreads();

        if (c + 2 < NITER) {
            const uint32_t nst = smb + (uint32_t)((c + 2) % NSTAGE) * STAGE;
            cp_A(c + 2, k, b0, nst);
            cp_B(c + 2, k, n0, nst);
            asm volatile("cp.async.commit_group;");
        }

        const uint32_t As = st, Bh = st + A_BYTES;
#pragma unroll
        for (int kk = 0; kk < 4; kk++) {
            uint32_t ah[4][4];
#pragma unroll
            for (int mb = 0; mb < 4; mb++)
                ldsm4(ah[mb], As + (uint32_t)((wm + mb * 16 + row16) * (SA * 2) +
                                              (kk * 16 + seg8) * 2));
#pragma unroll
            for (int p = 0; p < 2; p++) {
                uint32_t bh[4];
                ldsm4t(bh, Bh + (uint32_t)((kk * 16 + row16) * (SB * 2) +
                                           (wn + p * 16 + seg8) * 2));
#pragma unroll
                for (int mb = 0; mb < 4; mb++) {
                    mma16816(acc[mb][2 * p],     ah[mb], bh[0], bh[1]);
                    mma16816(acc[mb][2 * p + 1], ah[mb], bh[2], bh[3]);
                }
            }
        }
    }

    // Epilogue: tanh -> smem C tile + per-row partial stats.
    __syncthreads();
    {
        __half* cs = (__half*)sm;          // [BM][SVC] = 34816B
        float* s_ps = (float*)(sm + 35840);            // [128][4]
        float* s_pq = (float*)(sm + 35840 + 2048);     // [128][4]
        const int q = lane >> 2, c2 = (lane & 3) * 2;
        const int wj = wid & 3;
#pragma unroll
        for (int mb = 0; mb < 4; mb++) {
            const int r0 = wm + mb * 16 + q;
            float ps0 = 0.f, ps1 = 0.f, pq0 = 0.f, pq1 = 0.f;
#pragma unroll
            for (int nb = 0; nb < 4; nb++) {
                const int e = wn + nb * 8 + c2;
                float bb0 = s_b2[e], bb1 = s_b2[e + 1];
                float v0 = fast_tanh(acc[mb][nb][0] + bb0);
                float v1 = fast_tanh(acc[mb][nb][1] + bb1);
                float v2 = fast_tanh(acc[mb][nb][2] + bb0);
                float v3 = fast_tanh(acc[mb][nb][3] + bb1);
                *(__half2*)&cs[r0 * SVC + e]       = __floats2half2_rn(v0, v1);
                *(__half2*)&cs[(r0 + 8) * SVC + e] = __floats2half2_rn(v2, v3);
                ps0 += v0 + v1; ps1 += v2 + v3;
                pq0 += v0 * v0 + v1 * v1; pq1 += v2 * v2 + v3 * v3;
            }
            ps0 += __shfl_xor_sync(0xffffffffu, ps0, 1);
            ps0 += __shfl_xor_sync(0xffffffffu, ps0, 2);
            pq0 += __shfl_xor_sync(0xffffffffu, pq0, 1);
            pq0 += __shfl_xor_sync(0xffffffffu, pq0, 2);
            ps1 += __shfl_xor_sync(0xffffffffu, ps1, 1);
            ps1 += __shfl_xor_sync(0xffffffffu, ps1, 2);
            pq1 += __shfl_xor_sync(0xffffffffu, pq1, 1);
            pq1 += __shfl_xor_sync(0xffffffffu, pq1, 2);
            if ((lane & 3) == 0) {
                s_ps[r0 * 4 + wj] = ps0;
                s_pq[r0 * 4 + wj] = pq0;
                s_ps[(r0 + 8) * 4 + wj] = ps1;
                s_pq[(r0 + 8) * 4 + wj] = pq1;
            }
        }
        __syncthreads();
#pragma unroll
        for (int i = 0; i < 8; i++) {
            int idx = tid + i * 256;
            int row = idx >> 4, seg = idx & 15;
            uint4 v = *(uint4*)&cs[row * SVC + seg * 8];
            *(uint4*)&g_raw[((size_t)(b0 + row) * K_SZ + k) * D_SZ + n0 + seg * 8] = v;
        }
        if (tid < BM) {
            float su = s_ps[tid * 4] + s_ps[tid * 4 + 1] +
                       s_ps[tid * 4 + 2] + s_ps[tid * 4 + 3];
            float sq = s_pq[tid * 4] + s_pq[tid * 4 + 1] +
                       s_pq[tid * 4 + 2] + s_pq[tid * 4 + 3];
            g_psum[ny][(b0 + tid) * K_SZ + k] = su;
            g_psq[ny][(b0 + tid) * K_SZ + k] = sq;
        }
    }
}

// ---------------------------------------------------------------------------
// Combine: stats from GEMM partials; weighted sum straight from g_raw.
// ---------------------------------------------------------------------------
__global__ void __launch_bounds__(256) combine_kernel(
    const float* __restrict__ x_l, const float* __restrict__ ln_g,
    const float* __restrict__ ln_b, const float* __restrict__ theta0,
    float* __restrict__ out) {
    __shared__ float th[D_SZ];
    __shared__ float s_a[K_SZ], s_am[K_SZ];
    const int b = blockIdx.x;
    const int tid = threadIdx.x;

    if (tid < K_SZ) {
        int idx = b * K_SZ + tid;
        float su = g_psum[0][idx] + g_psum[1][idx] +
                   g_psum[2][idx] + g_psum[3][idx];
        float sq = g_psq[0][idx] + g_psq[1][idx] +
                   g_psq[2][idx] + g_psq[3][idx];
        float mu = su * (1.0f / (float)D_SZ);
        float var = sq * (1.0f / (float)D_SZ) - mu * mu;
        float rs = rsqrtf(var + LN_EPS);
        float a = g_gates[idx] * rs;
        s_a[tid] = a;
        s_am[tid] = a * mu;
    }
    __syncthreads();

    float cc = 0.0f;
#pragma unroll
    for (int kk = 0; kk < K_SZ; kk++) cc += s_am[kk];

    const __half2* rawb = (const __half2*)&g_raw[(size_t)b * K_SZ * D_SZ];
    {
        float ax = 0.0f, ay = 0.0f;
#pragma unroll
        for (int kk = 0; kk < K_SZ; kk++) {
            __half2 h = __ldcs(&rawb[kk * (D_SZ / 2) + tid]);
            float2 f = __half22float2(h);
            ax = fmaf(s_a[kk], f.x, ax);
            ay = fmaf(s_a[kk], f.y, ay);
        }
        float2 lg = *(const float2*)&ln_g[2 * tid];
        float2 lb = *(const float2*)&ln_b[2 * tid];
        float2 t0 = *(const float2*)&theta0[2 * tid];
        float tx = fmaf(lg.x, ax - cc, lb.x) + t0.x;
        float ty = fmaf(lg.y, ay - cc, lb.y) + t0.y;
        th[2 * tid] = tx;
        th[2 * tid + 1] = ty;
        *(float2*)&out[(size_t)B_SZ * XP_DIM + (size_t)b * D_SZ + 2 * tid] =
            make_float2(tx, ty);
    }
    __syncthreads();

    if (tid < XP_DIM) {
        float xp = 0.0f;
#pragma unroll
        for (int i = 0; i < IN_DIM; i++)
            xp = fmaf(x_l[b * IN_DIM + i], th[i * XP_DIM + tid], xp);
        out[b * XP_DIM + tid] = xp;
    }
}

// ---------------------------------------------------------------------------
extern "C" void kernel_launch(void* const* d_in, const int* in_sizes, int n_in,
                              void* d_out, int out_size) {
    const float* h_prev = (const float*)d_in[0];
    const float* x_l    = (const float*)d_in[1];
    const float* x_ext  = (const float*)d_in[2];
    const float* w1     = (const float*)d_in[3];
    const float* b1     = (const float*)d_in[4];
    const float* w2     = (const float*)d_in[5];
    const float* b2     = (const float*)d_in[6];
    const float* gw1    = (const float*)d_in[7];
    const float* gb1    = (const float*)d_in[8];
    const float* gw2    = (const float*)d_in[9];
    const float* gb2    = (const float*)d_in[10];
    const float* ln_g   = (const float*)d_in[11];
    const float* ln_b   = (const float*)d_in[12];
    const float* th0    = (const float*)d_in[13];
    float* out = (float*)d_out;

    cudaFuncSetAttribute(expert_gemm_kernel,
                         cudaFuncAttributeMaxDynamicSharedMemorySize, GEMM_SMEM);

    prep_kernel<<<NB_PREP, 256>>>(w2, x_ext, w1, b1, h_prev,
                                  gw1, gb1, gw2, gb2);
    expert_gemm_kernel<<<dim3(B_SZ / BM, NYB, K_SZ), 256, GEMM_SMEM>>>(b2);
    combine_kernel<<<B_SZ, 256>>>(x_l, ln_g, ln_b, th0, out);
}